// round 8
// baseline (speedup 1.0000x reference)
#include <cuda_runtime.h>
#include <cstdint>
#include <cstddef>
#include <math.h>

#define S    4096
#define L    16
#define H    512
#define EC   128
#define EW   512
#define HH   256
#define G4H  2048   // 4*H
#define G4HH 1024   // 4*HH
#define NPOS 64
#define NNER 32
#define KCAT 640    // EC + H

typedef unsigned long long ull;

// ---------------- scratch (device globals; no dynamic allocation) ----------------
__device__ float g_Xc[(size_t)L * S * EC];     // [t][slot][e]  char embeddings, sorted order
__device__ float g_hA[(size_t)S * H];          // char LSTM hidden ping
__device__ float g_hB[(size_t)S * H];          // char LSTM hidden pong
__device__ float g_c [(size_t)S * H];          // char LSTM cell (sorted order)
__device__ float g_wc [(size_t)S * (EW + H)];  // word LSTM input [S,1024] (orig order)
__device__ float g_xgf[(size_t)S * G4HH];      // precomputed x-gates fwd
__device__ float g_xgb[(size_t)S * G4HH];      // precomputed x-gates bwd
__device__ float g_out[(size_t)S * H];         // bi-LSTM output [S,512]
__device__ float g_Wcat[(size_t)G4H * KCAT];   // permuted concat(Wih_c|Whh_c), gate-interleaved
__device__ float g_biasP[G4H];                 // permuted bih_c+bhh_c
__device__ int   g_perm[S];                    // sorted slot -> original index
__device__ int   g_inv[S];                     // original index -> sorted slot
__device__ int   g_lensS[S];                   // lens in sorted order (descending)
__device__ int   g_cnt[L];                     // cnt[t] = #words with len > t

// fast transcendentals (err ~1e-7 rel; tolerance is 1e-3)
__device__ __forceinline__ float fsig(float x) {
    return __fdividef(1.f, 1.f + __expf(-x));
}
__device__ __forceinline__ float ftanh(float x) {
    return 1.f - __fdividef(2.f, __expf(2.f * x) + 1.f);
}

__device__ __forceinline__ ull pack2(float x, float y) {
    ull r; asm("mov.b64 %0,{%1,%2};" : "=l"(r) : "f"(x), "f"(y)); return r;
}
__device__ __forceinline__ void unpack2(ull v, float& x, float& y) {
    asm("mov.b64 {%0,%1},%2;" : "=f"(x), "=f"(y) : "l"(v));
}
__device__ __forceinline__ ull ffma2(ull a, ull b, ull c) {
    ull d; asm("fma.rn.f32x2 %0,%1,%2,%3;" : "=l"(d) : "l"(a), "l"(b), "l"(c)); return d;
}

// ---------------- counting sort by char length (descending) ----------------
__global__ void k_sort(const int* __restrict__ lens) {
    __shared__ int hist[17], off[17];
    int tid = threadIdx.x;
    if (tid < 17) hist[tid] = 0;
    __syncthreads();
    for (int s = tid; s < S; s += blockDim.x) atomicAdd(&hist[lens[s]], 1);
    __syncthreads();
    if (tid == 0) {
        int acc = 0;
        for (int l = 16; l >= 1; --l) { off[l] = acc; acc += hist[l]; }
        for (int t = 0; t < L; ++t) g_cnt[t] = off[t + 1] + hist[t + 1];
    }
    __syncthreads();
    for (int s = tid; s < S; s += blockDim.x) {
        int l = lens[s];
        int pos = atomicAdd(&off[l], 1);
        g_perm[pos] = s;
        g_inv[s] = pos;
        g_lensS[pos] = l;
    }
}

// ---------------- fused prep: permuted weights + bias + h/c init -----------------
__global__ void k_prep_all(const float* __restrict__ Wih_c,
                           const float* __restrict__ Whh_c,
                           const float* __restrict__ bih_c,
                           const float* __restrict__ bhh_c,
                           const int*   __restrict__ feat_seq,
                           const float* __restrict__ prefix_emb) {
    int b = blockIdx.x;
    if (b < 5120) {
        int idx = b * 256 + threadIdx.x;               // < 2048*640
        int n = idx / KCAT, k = idx % KCAT;
        int jh = n >> 2, g = n & 3;
        int row = g * H + jh;
        g_Wcat[idx] = (k < EC) ? Wih_c[(size_t)row * EC + k]
                               : Whh_c[(size_t)row * H + (k - EC)];
    } else if (b < 5128) {
        int n = (b - 5120) * 256 + threadIdx.x;        // < 2048
        int jh = n >> 2, g = n & 3;
        int row = g * H + jh;
        g_biasP[n] = bih_c[row] + bhh_c[row];
    } else {
        int idx = (b - 5128) * 256 + threadIdx.x;      // < S*128 (float4 units)
        int j4 = idx & 127;
        int slot = idx >> 7;
        int s = g_perm[slot];
        reinterpret_cast<float4*>(g_hA)[idx] =
            reinterpret_cast<const float4*>(prefix_emb)[(size_t)feat_seq[s] * 128 + j4];
        reinterpret_cast<float4*>(g_c)[idx] = make_float4(0.f, 0.f, 0.f, 0.f);
    }
}

// ---------------- embedding gather (sorted order, float4) ----------------
__global__ void k_gather_xc(const int* __restrict__ chars,
                            const float* __restrict__ char_emb) {
    int idx = blockIdx.x * blockDim.x + threadIdx.x;   // < L*S*32
    int e4 = idx & 31;
    int slot = (idx >> 5) & (S - 1);
    int t = idx >> 17;
    int s = g_perm[slot];
    reinterpret_cast<float4*>(g_Xc)[idx] =
        reinterpret_cast<const float4*>(char_emb)[(size_t)chars[s * L + t] * 32 + e4];
}

__global__ void k_build_wc(const int* __restrict__ word_seq,
                           const float* __restrict__ word_emb) {
    int idx = blockIdx.x * blockDim.x + threadIdx.x;   // < S*256
    int k4 = idx & 255;
    int s = idx >> 8;
    float4 v;
    if (k4 < 128) {
        v = reinterpret_cast<const float4*>(word_emb)[(size_t)word_seq[s] * 128 + k4];
    } else {
        int slot = g_inv[s];
        int len = g_lensS[slot];
        const float4* hp = reinterpret_cast<const float4*>((len & 1) ? g_hB : g_hA);
        v = hp[(size_t)slot * 128 + (k4 - 128)];
    }
    reinterpret_cast<float4*>(g_wc)[idx] = v;
}

// ---------------- fused char-LSTM step: gates GEMM + cell update ----------------
// 128x128 block tile, 8x8 thread tile (FFMA2), double-buffered smem.
__global__ __launch_bounds__(256)
void k_char_step(const float* __restrict__ Xc_t,
                 const float* __restrict__ hcur,
                 float* __restrict__ hnxt, int t) {
    const int cnt = g_cnt[t];
    const int m0 = blockIdx.y * 128;
    if (m0 >= cnt) return;
    const int n0 = blockIdx.x * 128;

    __shared__ __align__(16) float As[2][8][128];
    __shared__ __align__(16) float Bs[2][8][128];

    const int tid = threadIdx.x;
    const int row = tid >> 1;             // 0..127
    const int kc  = (tid & 1) * 4;        // 0 or 4
    const int tx  = tid & 15, ty = tid >> 4;

    ull acc2[8][4];
    #pragma unroll
    for (int i = 0; i < 8; i++)
        #pragma unroll
        for (int j = 0; j < 4; j++) acc2[i][j] = 0ULL;

    float4 pA, pB;
    auto loadT = [&](int kt) {
        int k = kt + kc;
        const float* srcA = (k < EC)
            ? (Xc_t + (size_t)(m0 + row) * EC + k)
            : (hcur + (size_t)(m0 + row) * H + (k - EC));
        pA = *reinterpret_cast<const float4*>(srcA);
        pB = *reinterpret_cast<const float4*>(g_Wcat + (size_t)(n0 + row) * KCAT + k);
    };
    auto stsT = [&](int buf) {
        As[buf][kc + 0][row] = pA.x; As[buf][kc + 1][row] = pA.y;
        As[buf][kc + 2][row] = pA.z; As[buf][kc + 3][row] = pA.w;
        Bs[buf][kc + 0][row] = pB.x; Bs[buf][kc + 1][row] = pB.y;
        Bs[buf][kc + 2][row] = pB.z; Bs[buf][kc + 3][row] = pB.w;
    };

    loadT(0);
    stsT(0);
    __syncthreads();

    int cur = 0;
    for (int kt = 0; kt < KCAT; kt += 8) {
        bool more = (kt + 8) < KCAT;
        if (more) loadT(kt + 8);
        #pragma unroll
        for (int kk = 0; kk < 8; kk++) {
            float a[8];
            *reinterpret_cast<float4*>(&a[0]) = *reinterpret_cast<const float4*>(&As[cur][kk][ty * 8]);
            *reinterpret_cast<float4*>(&a[4]) = *reinterpret_cast<const float4*>(&As[cur][kk][ty * 8 + 4]);
            ull b2[4];
            const ull* bp = reinterpret_cast<const ull*>(&Bs[cur][kk][tx * 8]);
            b2[0] = bp[0]; b2[1] = bp[1]; b2[2] = bp[2]; b2[3] = bp[3];
            #pragma unroll
            for (int i = 0; i < 8; i++) {
                ull ad = pack2(a[i], a[i]);
                #pragma unroll
                for (int j = 0; j < 4; j++)
                    acc2[i][j] = ffma2(ad, b2[j], acc2[i][j]);
            }
        }
        if (more) {
            stsT(cur ^ 1);
            __syncthreads();
            cur ^= 1;
        }
    }

    float bn[8];
    #pragma unroll
    for (int j = 0; j < 8; j++) bn[j] = g_biasP[n0 + tx * 8 + j];
    const int jh0 = (n0 >> 2) + tx * 2;

    #pragma unroll
    for (int i = 0; i < 8; i++) {
        int m = m0 + ty * 8 + i;
        if (t < g_lensS[m]) {
            float v0, v1, v2, v3, v4, v5, v6, v7;
            unpack2(acc2[i][0], v0, v1); unpack2(acc2[i][1], v2, v3);
            unpack2(acc2[i][2], v4, v5); unpack2(acc2[i][3], v6, v7);
            size_t ci = (size_t)m * H + jh0;
            {
                float iv = v0 + bn[0], fv = v1 + bn[1], gv = v2 + bn[2], ov = v3 + bn[3];
                float c = g_c[ci];
                c = fsig(fv) * c + fsig(iv) * ftanh(gv);
                g_c[ci] = c;
                hnxt[ci] = fsig(ov) * ftanh(c);
            }
            {
                float iv = v4 + bn[4], fv = v5 + bn[5], gv = v6 + bn[6], ov = v7 + bn[7];
                float c = g_c[ci + 1];
                c = fsig(fv) * c + fsig(iv) * ftanh(gv);
                g_c[ci + 1] = c;
                hnxt[ci + 1] = fsig(ov) * ftanh(c);
            }
        }
    }
}

// ---------------- merged x-gate GEMM (fwd + bwd via blockIdx.z) ----------------
__global__ __launch_bounds__(256)
void gemm_xg(const float* __restrict__ A1,
             const float* __restrict__ Bf, const float* __restrict__ Bb,
             const float* __restrict__ b1f, const float* __restrict__ b2f,
             const float* __restrict__ b1b, const float* __restrict__ b2b,
             float* __restrict__ Cf, float* __restrict__ Cb) {
    const int K1 = EW + H, N = G4HH;
    const int BM = 128, BN = 128, BK = 8;
    const float* B1 = blockIdx.z ? Bb : Bf;
    const float* b1 = blockIdx.z ? b1b : b1f;
    const float* b2 = blockIdx.z ? b2b : b2f;
    float* C = blockIdx.z ? Cb : Cf;

    __shared__ __align__(16) float As[BK][BM];
    __shared__ __align__(16) float Bs[BK][BN];
    int tid = threadIdx.x;
    int m0 = blockIdx.y * BM;
    int n0 = blockIdx.x * BN;
    int aRow = tid >> 1, aCol = (tid & 1) * 4;
    int tx = tid & 15, ty = tid >> 4;

    ull acc2[8][4];
    #pragma unroll
    for (int i = 0; i < 8; i++)
        #pragma unroll
        for (int j = 0; j < 4; j++) acc2[i][j] = 0ULL;

    for (int kt = 0; kt < K1; kt += BK) {
        int k = kt + aCol;
        {
            float4 v = *reinterpret_cast<const float4*>(A1 + (size_t)(m0 + aRow) * K1 + k);
            As[aCol + 0][aRow] = v.x; As[aCol + 1][aRow] = v.y;
            As[aCol + 2][aRow] = v.z; As[aCol + 3][aRow] = v.w;
        }
        {
            float4 v = *reinterpret_cast<const float4*>(B1 + (size_t)(n0 + aRow) * K1 + k);
            Bs[aCol + 0][aRow] = v.x; Bs[aCol + 1][aRow] = v.y;
            Bs[aCol + 2][aRow] = v.z; Bs[aCol + 3][aRow] = v.w;
        }
        __syncthreads();
        #pragma unroll
        for (int kk = 0; kk < BK; kk++) {
            float a[8];
            *reinterpret_cast<float4*>(&a[0]) = *reinterpret_cast<const float4*>(&As[kk][ty * 8]);
            *reinterpret_cast<float4*>(&a[4]) = *reinterpret_cast<const float4*>(&As[kk][ty * 8 + 4]);
            ull b2r[4];
            const ull* bp = reinterpret_cast<const ull*>(&Bs[kk][tx * 8]);
            b2r[0] = bp[0]; b2r[1] = bp[1]; b2r[2] = bp[2]; b2r[3] = bp[3];
            #pragma unroll
            for (int i = 0; i < 8; i++) {
                ull ad = pack2(a[i], a[i]);
                #pragma unroll
                for (int j = 0; j < 4; j++)
                    acc2[i][j] = ffma2(ad, b2r[j], acc2[i][j]);
            }
        }
        __syncthreads();
    }
    #pragma unroll
    for (int i = 0; i < 8; i++) {
        int m = m0 + ty * 8 + i;
        #pragma unroll
        for (int jj = 0; jj < 4; jj++) {
            float lo, hi;
            unpack2(acc2[i][jj], lo, hi);
            int n = n0 + tx * 8 + jj * 2;
            C[(size_t)m * N + n]     = lo + b1[n] + b2[n];
            C[(size_t)m * N + n + 1] = hi + b1[n + 1] + b2[n + 1];
        }
    }
}

// ---------------- word bi-LSTM recurrence: 2 clusters of 8 CTAs, 512 thr ----------
// R7 proven layout (broadcast hb reads, q = tid>>7). Cross-CTA sync is now a
// per-CTA mbarrier (count=8): after the CTA-wide __syncthreads (which orders all
// hb reads), lanes 0-7 issue one release-arrive to each peer; everyone acquires
// on the local barrier. A CTA's arrive doubles as its read-completion signal, so
// the next step's overwrites of the previous buffer cannot race lagging readers.
__device__ __forceinline__ void mbar_wait_acq(unsigned addr, unsigned ph) {
    asm volatile(
        "{\n\t"
        ".reg .pred P;\n\t"
        "WAIT_%=:\n\t"
        "mbarrier.try_wait.parity.acquire.cluster.shared::cta.b64 P, [%0], %1, 0x989680;\n\t"
        "@P bra.uni DONE_%=;\n\t"
        "bra.uni WAIT_%=;\n\t"
        "DONE_%=:\n\t"
        "}"
        :: "r"(addr), "r"(ph) : "memory");
}

__global__ void __cluster_dims__(8, 1, 1) __launch_bounds__(512, 1)
k_word_lstm(const float* __restrict__ Whh_f, const float* __restrict__ Whh_b) {
    __shared__ __align__(16) float hb[2][HH];
    __shared__ float partial[512];
    __shared__ float gbuf[128];
    __shared__ __align__(8) ull mbar;

    unsigned rank;
    asm("mov.u32 %0, %%cluster_ctarank;" : "=r"(rank));
    int dir = blockIdx.x / 8;                   // 0 = fwd, 1 = bwd
    const float* Whh = dir ? Whh_b : Whh_f;
    const float* xg  = dir ? g_xgb : g_xgf;

    int tid = threadIdx.x;
    int p   = tid & 127;       // gate-row within CTA: gate*32 + jj
    int q   = tid >> 7;        // k-quarter (0..3)
    int gte = p >> 5;
    int jj  = p & 31;
    int grow = gte * HH + (int)rank * 32 + jj;  // row in Whh[1024][256], also xg column

    ull w2[32];
    const float4* wsrc = reinterpret_cast<const float4*>(Whh + (size_t)grow * HH + q * 64);
    #pragma unroll
    for (int i = 0; i < 16; i++) {
        float4 f = wsrc[i];
        w2[2 * i]     = pack2(f.x, f.y);
        w2[2 * i + 1] = pack2(f.z, f.w);
    }

    unsigned mbar_off = (unsigned)__cvta_generic_to_shared(&mbar);
    if (tid == 0) {
        asm volatile("mbarrier.init.shared.b64 [%0], %1;"
                     :: "r"(mbar_off), "r"(8) : "memory");
    }
    // precompute remote h-store addresses (lanes 0-31) and remote mbar (lanes 0-7)
    unsigned raA[8], raB[8], rmb = 0;
    {
        unsigned loff0 = (unsigned)__cvta_generic_to_shared(&hb[0][rank * 32 + (tid & 31)]);
        unsigned loff1 = (unsigned)__cvta_generic_to_shared(&hb[1][rank * 32 + (tid & 31)]);
        #pragma unroll
        for (int peer = 0; peer < 8; ++peer) {
            asm("mapa.shared::cluster.u32 %0, %1, %2;" : "=r"(raA[peer]) : "r"(loff0), "r"(peer));
            asm("mapa.shared::cluster.u32 %0, %1, %2;" : "=r"(raB[peer]) : "r"(loff1), "r"(peer));
        }
        asm("mapa.shared::cluster.u32 %0, %1, %2;" : "=r"(rmb) : "r"(mbar_off), "r"(tid & 7));
    }

    if (tid < HH) hb[0][tid] = 0.f;
    __syncthreads();
    asm volatile("barrier.cluster.arrive.aligned;" ::: "memory");
    asm volatile("barrier.cluster.wait.aligned;"   ::: "memory");

    float c_reg = 0.f;
    int lane = tid & 31;
    int par = 0;
    // prefetch x-gate for t=0 (tid<128 lanes)
    float xv = (q == 0) ? __ldg(&xg[(size_t)(dir ? (S - 1) : 0) * G4HH + grow]) : 0.f;

    for (int t = 0; t < S; ++t) {
        int row = dir ? (S - 1 - t) : t;

        const ulonglong2* hv = reinterpret_cast<const ulonglong2*>(&hb[par][q * 64]);
        ull a0 = 0ULL, a1 = 0ULL, a2 = 0ULL, a3 = 0ULL;
        #pragma unroll
        for (int i = 0; i < 16; i += 2) {
            ulonglong2 h0 = hv[i], h1 = hv[i + 1];
            a0 = ffma2(w2[2 * i + 0], h0.x, a0);
            a1 = ffma2(w2[2 * i + 1], h0.y, a1);
            a2 = ffma2(w2[2 * i + 2], h1.x, a2);
            a3 = ffma2(w2[2 * i + 3], h1.y, a3);
        }
        float l0, h0f, l1, h1f, l2, h2f, l3, h3f;
        unpack2(a0, l0, h0f); unpack2(a1, l1, h1f);
        unpack2(a2, l2, h2f); unpack2(a3, l3, h3f);
        partial[tid] = ((l0 + h0f) + (l1 + h1f)) + ((l2 + h2f) + (l3 + h3f));

        // rolling prefetch of next x-gate (independent of barriers)
        float xvn = 0.f;
        if (q == 0 && t + 1 < S) {
            int rn = dir ? (S - 2 - t) : (t + 1);
            xvn = __ldg(&xg[(size_t)rn * G4HH + grow]);
        }
        __syncthreads();
        if (tid < 128) {
            float gpre = partial[p] + partial[p + 128] + partial[p + 256]
                       + partial[p + 384] + xv;
            gbuf[p] = (gte == 2) ? ftanh(gpre) : fsig(gpre);
        }
        __syncthreads();
        if (tid < 32) {
            float iv = gbuf[lane], fv = gbuf[32 + lane];
            float gg = gbuf[64 + lane], ov = gbuf[96 + lane];
            c_reg = fv * c_reg + iv * gg;
            float hnew = ov * ftanh(c_reg);
            g_out[(size_t)row * H + dir * HH + rank * 32 + lane] = hnew;
            if (par == 0) {
                #pragma unroll
                for (int peer = 0; peer < 8; ++peer)
                    asm volatile("st.shared::cluster.f32 [%0], %1;"
                                 :: "r"(raB[peer]), "f"(hnew) : "memory");
            } else {
                #pragma unroll
                for (int peer = 0; peer < 8; ++peer)
                    asm volatile("st.shared::cluster.f32 [%0], %1;"
                                 :: "r"(raA[peer]), "f"(hnew) : "memory");
            }
            __syncwarp();
            if (lane < 8)
                asm volatile("mbarrier.arrive.release.cluster.shared::cluster.b64 _, [%0];"
                             :: "r"(rmb) : "memory");
        }
        mbar_wait_acq(mbar_off, (unsigned)(t & 1));
        par ^= 1;
        xv = xvn;
    }
    asm volatile("barrier.cluster.arrive.aligned;" ::: "memory");
    asm volatile("barrier.cluster.wait.aligned;"   ::: "memory");
}

// ---------------- output heads: logits + log_softmax ----------------
__global__ void k_logits(const float* __restrict__ W,   // [C,512]
                         const float* __restrict__ bias,
                         float* __restrict__ dst, int C) {
    __shared__ float row[H];
    __shared__ float red[64];
    int s = blockIdx.x, tid = threadIdx.x;
    for (int k = tid; k < H; k += blockDim.x) row[k] = g_out[(size_t)s * H + k];
    __syncthreads();
    float acc = bias[tid];
    const float4* w4 = reinterpret_cast<const float4*>(W + (size_t)tid * H);
    const float4* r4 = reinterpret_cast<const float4*>(row);
    #pragma unroll 8
    for (int q = 0; q < H / 4; q++) {
        float4 w = w4[q], r = r4[q];
        acc += w.x * r.x + w.y * r.y + w.z * r.z + w.w * r.w;
    }
    red[tid] = acc;
    __syncthreads();
    for (int off = C >> 1; off; off >>= 1) {
        if (tid < off) red[tid] = fmaxf(red[tid], red[tid + off]);
        __syncthreads();
    }
    float mx = red[0];
    __syncthreads();
    red[tid] = expf(acc - mx);
    __syncthreads();
    for (int off = C >> 1; off; off >>= 1) {
        if (tid < off) red[tid] += red[tid + off];
        __syncthreads();
    }
    float lse = mx + logf(red[0]);
    dst[(size_t)s * C + tid] = acc - lse;
}

// ---------------- launch ----------------
extern "C" void kernel_launch(void* const* d_in, const int* in_sizes, int n_in,
                              void* d_out, int out_size) {
    const int*   word_seq   = (const int*)  d_in[0];
    const int*   chars      = (const int*)  d_in[1];
    const int*   char_lens  = (const int*)  d_in[2];
    const int*   feat_seq   = (const int*)  d_in[3];
    const float* char_emb   = (const float*)d_in[4];
    const float* word_emb   = (const float*)d_in[5];
    const float* prefix_emb = (const float*)d_in[6];
    const float* Wih_c = (const float*)d_in[7];
    const float* Whh_c = (const float*)d_in[8];
    const float* bih_c = (const float*)d_in[9];
    const float* bhh_c = (const float*)d_in[10];
    const float* Wih_f = (const float*)d_in[11];
    const float* Whh_f = (const float*)d_in[12];
    const float* bih_f = (const float*)d_in[13];
    const float* bhh_f = (const float*)d_in[14];
    const float* Wih_b = (const float*)d_in[15];
    const float* Whh_b = (const float*)d_in[16];
    const float* bih_b = (const float*)d_in[17];
    const float* bhh_b = (const float*)d_in[18];
    const float* Wpos  = (const float*)d_in[19];
    const float* bpos  = (const float*)d_in[20];
    const float* Wner  = (const float*)d_in[21];
    const float* bner  = (const float*)d_in[22];
    float* out = (float*)d_out;

    float *p_Xc, *p_hA, *p_hB, *p_wc, *p_xgf, *p_xgb;
    cudaGetSymbolAddress((void**)&p_Xc,  g_Xc);
    cudaGetSymbolAddress((void**)&p_hA,  g_hA);
    cudaGetSymbolAddress((void**)&p_hB,  g_hB);
    cudaGetSymbolAddress((void**)&p_wc,  g_wc);
    cudaGetSymbolAddress((void**)&p_xgf, g_xgf);
    cudaGetSymbolAddress((void**)&p_xgb, g_xgb);

    // launches 1-3: sort, fused prep, gather
    k_sort<<<1, 256>>>(char_lens);
    k_prep_all<<<5120 + 8 + 2048, 256>>>(Wih_c, Whh_c, bih_c, bhh_c,
                                         feat_seq, prefix_emb);
    k_gather_xc<<<(L * S * 32) / 256, 256>>>(chars, char_emb);

    // char LSTM: 16 fused steps, h ping-pong, early-exit beyond cnt[t]
    dim3 gridC(G4H / 128, S / 128);
    for (int t = 0; t < L; ++t) {
        float* hcur = (t & 1) ? p_hB : p_hA;
        float* hnxt = (t & 1) ? p_hA : p_hB;
        k_char_step<<<gridC, 256>>>(p_Xc + (size_t)t * S * EC, hcur, hnxt, t);
    }

    // word LSTM input + merged x-gate precompute (fwd+bwd in one launch)
    k_build_wc<<<(S * 256) / 256, 256>>>(word_seq, word_emb);
    dim3 gridX(G4HH / 128, S / 128, 2);
    gemm_xg<<<gridX, 256>>>(p_wc, Wih_f, Wih_b,
                            bih_f, bhh_f, bih_b, bhh_b,
                            p_xgf, p_xgb);

    // sequential bi-LSTM recurrence (2 clusters of 8 CTAs, fwd + bwd concurrent)
    k_word_lstm<<<16, 512>>>(Whh_f, Whh_b);

    // output heads
    k_logits<<<S, NPOS>>>(Wpos, bpos, out, NPOS);
    k_logits<<<S, NNER>>>(Wner, bner, out + (size_t)S * NPOS, NNER);

    (void)in_sizes; (void)n_in; (void)out_size;
}

// round 9
// speedup vs baseline: 1.0416x; 1.0416x over previous
#include <cuda_runtime.h>
#include <cstdint>
#include <cstddef>
#include <math.h>

#define S    4096
#define L    16
#define H    512
#define EC   128
#define EW   512
#define HH   256
#define G4H  2048   // 4*H
#define G4HH 1024   // 4*HH
#define NPOS 64
#define NNER 32
#define KCAT 640    // EC + H

typedef unsigned long long ull;

// ---------------- scratch (device globals; no dynamic allocation) ----------------
__device__ float g_Xc[(size_t)L * S * EC];     // [t][slot][e]  char embeddings, sorted order
__device__ float g_hA[(size_t)S * H];          // char LSTM hidden ping
__device__ float g_hB[(size_t)S * H];          // char LSTM hidden pong
__device__ float g_c [(size_t)S * H];          // char LSTM cell (sorted order)
__device__ float g_wc [(size_t)S * (EW + H)];  // word LSTM input [S,1024] (orig order)
__device__ float g_xgf[(size_t)S * G4HH];      // precomputed x-gates fwd
__device__ float g_xgb[(size_t)S * G4HH];      // precomputed x-gates bwd
__device__ float g_out[(size_t)S * H];         // bi-LSTM output [S,512]
__device__ float g_Wcat[(size_t)G4H * KCAT];   // permuted concat(Wih_c|Whh_c), gate-interleaved
__device__ float g_biasP[G4H];                 // permuted bih_c+bhh_c
__device__ int   g_perm[S];                    // sorted slot -> original index
__device__ int   g_inv[S];                     // original index -> sorted slot
__device__ int   g_lensS[S];                   // lens in sorted order (descending)
__device__ int   g_cnt[L];                     // cnt[t] = #words with len > t

// fast transcendentals (err ~1e-7 rel; tolerance is 1e-3)
__device__ __forceinline__ float fsig(float x) {
    return __fdividef(1.f, 1.f + __expf(-x));
}
__device__ __forceinline__ float ftanh(float x) {
    return 1.f - __fdividef(2.f, __expf(2.f * x) + 1.f);
}

__device__ __forceinline__ ull pack2(float x, float y) {
    ull r; asm("mov.b64 %0,{%1,%2};" : "=l"(r) : "f"(x), "f"(y)); return r;
}
__device__ __forceinline__ void unpack2(ull v, float& x, float& y) {
    asm("mov.b64 {%0,%1},%2;" : "=f"(x), "=f"(y) : "l"(v));
}
__device__ __forceinline__ ull ffma2(ull a, ull b, ull c) {
    ull d; asm("fma.rn.f32x2 %0,%1,%2,%3;" : "=l"(d) : "l"(a), "l"(b), "l"(c)); return d;
}

// ---------------- counting sort by char length (descending) ----------------
__global__ void k_sort(const int* __restrict__ lens) {
    __shared__ int hist[17], off[17];
    int tid = threadIdx.x;
    if (tid < 17) hist[tid] = 0;
    __syncthreads();
    for (int s = tid; s < S; s += blockDim.x) atomicAdd(&hist[lens[s]], 1);
    __syncthreads();
    if (tid == 0) {
        int acc = 0;
        for (int l = 16; l >= 1; --l) { off[l] = acc; acc += hist[l]; }
        for (int t = 0; t < L; ++t) g_cnt[t] = off[t + 1] + hist[t + 1];
    }
    __syncthreads();
    for (int s = tid; s < S; s += blockDim.x) {
        int l = lens[s];
        int pos = atomicAdd(&off[l], 1);
        g_perm[pos] = s;
        g_inv[s] = pos;
        g_lensS[pos] = l;
    }
}

// ---------------- fused prep: permuted weights + bias + h/c init -----------------
__global__ void k_prep_all(const float* __restrict__ Wih_c,
                           const float* __restrict__ Whh_c,
                           const float* __restrict__ bih_c,
                           const float* __restrict__ bhh_c,
                           const int*   __restrict__ feat_seq,
                           const float* __restrict__ prefix_emb) {
    int b = blockIdx.x;
    if (b < 5120) {
        int idx = b * 256 + threadIdx.x;               // < 2048*640
        int n = idx / KCAT, k = idx % KCAT;
        int jh = n >> 2, g = n & 3;
        int row = g * H + jh;
        g_Wcat[idx] = (k < EC) ? Wih_c[(size_t)row * EC + k]
                               : Whh_c[(size_t)row * H + (k - EC)];
    } else if (b < 5128) {
        int n = (b - 5120) * 256 + threadIdx.x;        // < 2048
        int jh = n >> 2, g = n & 3;
        int row = g * H + jh;
        g_biasP[n] = bih_c[row] + bhh_c[row];
    } else {
        int idx = (b - 5128) * 256 + threadIdx.x;      // < S*128 (float4 units)
        int j4 = idx & 127;
        int slot = idx >> 7;
        int s = g_perm[slot];
        reinterpret_cast<float4*>(g_hA)[idx] =
            reinterpret_cast<const float4*>(prefix_emb)[(size_t)feat_seq[s] * 128 + j4];
        reinterpret_cast<float4*>(g_c)[idx] = make_float4(0.f, 0.f, 0.f, 0.f);
    }
}

// ---------------- embedding gather (sorted order, float4) ----------------
__global__ void k_gather_xc(const int* __restrict__ chars,
                            const float* __restrict__ char_emb) {
    int idx = blockIdx.x * blockDim.x + threadIdx.x;   // < L*S*32
    int e4 = idx & 31;
    int slot = (idx >> 5) & (S - 1);
    int t = idx >> 17;
    int s = g_perm[slot];
    reinterpret_cast<float4*>(g_Xc)[idx] =
        reinterpret_cast<const float4*>(char_emb)[(size_t)chars[s * L + t] * 32 + e4];
}

__global__ void k_build_wc(const int* __restrict__ word_seq,
                           const float* __restrict__ word_emb) {
    int idx = blockIdx.x * blockDim.x + threadIdx.x;   // < S*256
    int k4 = idx & 255;
    int s = idx >> 8;
    float4 v;
    if (k4 < 128) {
        v = reinterpret_cast<const float4*>(word_emb)[(size_t)word_seq[s] * 128 + k4];
    } else {
        int slot = g_inv[s];
        int len = g_lensS[slot];
        const float4* hp = reinterpret_cast<const float4*>((len & 1) ? g_hB : g_hA);
        v = hp[(size_t)slot * 128 + (k4 - 128)];
    }
    reinterpret_cast<float4*>(g_wc)[idx] = v;
}

// ---------------- fused char-LSTM step: gates GEMM + cell update ----------------
// 128x128 block tile, 8x8 thread tile (FFMA2), double-buffered smem.
__global__ __launch_bounds__(256)
void k_char_step(const float* __restrict__ Xc_t,
                 const float* __restrict__ hcur,
                 float* __restrict__ hnxt, int t) {
    const int cnt = g_cnt[t];
    const int m0 = blockIdx.y * 128;
    if (m0 >= cnt) return;
    const int n0 = blockIdx.x * 128;

    __shared__ __align__(16) float As[2][8][128];
    __shared__ __align__(16) float Bs[2][8][128];

    const int tid = threadIdx.x;
    const int row = tid >> 1;             // 0..127
    const int kc  = (tid & 1) * 4;        // 0 or 4
    const int tx  = tid & 15, ty = tid >> 4;

    ull acc2[8][4];
    #pragma unroll
    for (int i = 0; i < 8; i++)
        #pragma unroll
        for (int j = 0; j < 4; j++) acc2[i][j] = 0ULL;

    float4 pA, pB;
    auto loadT = [&](int kt) {
        int k = kt + kc;
        const float* srcA = (k < EC)
            ? (Xc_t + (size_t)(m0 + row) * EC + k)
            : (hcur + (size_t)(m0 + row) * H + (k - EC));
        pA = *reinterpret_cast<const float4*>(srcA);
        pB = *reinterpret_cast<const float4*>(g_Wcat + (size_t)(n0 + row) * KCAT + k);
    };
    auto stsT = [&](int buf) {
        As[buf][kc + 0][row] = pA.x; As[buf][kc + 1][row] = pA.y;
        As[buf][kc + 2][row] = pA.z; As[buf][kc + 3][row] = pA.w;
        Bs[buf][kc + 0][row] = pB.x; Bs[buf][kc + 1][row] = pB.y;
        Bs[buf][kc + 2][row] = pB.z; Bs[buf][kc + 3][row] = pB.w;
    };

    loadT(0);
    stsT(0);
    __syncthreads();

    int cur = 0;
    for (int kt = 0; kt < KCAT; kt += 8) {
        bool more = (kt + 8) < KCAT;
        if (more) loadT(kt + 8);
        #pragma unroll
        for (int kk = 0; kk < 8; kk++) {
            float a[8];
            *reinterpret_cast<float4*>(&a[0]) = *reinterpret_cast<const float4*>(&As[cur][kk][ty * 8]);
            *reinterpret_cast<float4*>(&a[4]) = *reinterpret_cast<const float4*>(&As[cur][kk][ty * 8 + 4]);
            ull b2[4];
            const ull* bp = reinterpret_cast<const ull*>(&Bs[cur][kk][tx * 8]);
            b2[0] = bp[0]; b2[1] = bp[1]; b2[2] = bp[2]; b2[3] = bp[3];
            #pragma unroll
            for (int i = 0; i < 8; i++) {
                ull ad = pack2(a[i], a[i]);
                #pragma unroll
                for (int j = 0; j < 4; j++)
                    acc2[i][j] = ffma2(ad, b2[j], acc2[i][j]);
            }
        }
        if (more) {
            stsT(cur ^ 1);
            __syncthreads();
            cur ^= 1;
        }
    }

    float bn[8];
    #pragma unroll
    for (int j = 0; j < 8; j++) bn[j] = g_biasP[n0 + tx * 8 + j];
    const int jh0 = (n0 >> 2) + tx * 2;

    #pragma unroll
    for (int i = 0; i < 8; i++) {
        int m = m0 + ty * 8 + i;
        if (t < g_lensS[m]) {
            float v0, v1, v2, v3, v4, v5, v6, v7;
            unpack2(acc2[i][0], v0, v1); unpack2(acc2[i][1], v2, v3);
            unpack2(acc2[i][2], v4, v5); unpack2(acc2[i][3], v6, v7);
            size_t ci = (size_t)m * H + jh0;
            {
                float iv = v0 + bn[0], fv = v1 + bn[1], gv = v2 + bn[2], ov = v3 + bn[3];
                float c = g_c[ci];
                c = fsig(fv) * c + fsig(iv) * ftanh(gv);
                g_c[ci] = c;
                hnxt[ci] = fsig(ov) * ftanh(c);
            }
            {
                float iv = v4 + bn[4], fv = v5 + bn[5], gv = v6 + bn[6], ov = v7 + bn[7];
                float c = g_c[ci + 1];
                c = fsig(fv) * c + fsig(iv) * ftanh(gv);
                g_c[ci + 1] = c;
                hnxt[ci + 1] = fsig(ov) * ftanh(c);
            }
        }
    }
}

// ---------------- merged x-gate GEMM (fwd + bwd via blockIdx.z) ----------------
__global__ __launch_bounds__(256)
void gemm_xg(const float* __restrict__ A1,
             const float* __restrict__ Bf, const float* __restrict__ Bb,
             const float* __restrict__ b1f, const float* __restrict__ b2f,
             const float* __restrict__ b1b, const float* __restrict__ b2b,
             float* __restrict__ Cf, float* __restrict__ Cb) {
    const int K1 = EW + H, N = G4HH;
    const int BM = 128, BN = 128, BK = 8;
    const float* B1 = blockIdx.z ? Bb : Bf;
    const float* b1 = blockIdx.z ? b1b : b1f;
    const float* b2 = blockIdx.z ? b2b : b2f;
    float* C = blockIdx.z ? Cb : Cf;

    __shared__ __align__(16) float As[BK][BM];
    __shared__ __align__(16) float Bs[BK][BN];
    int tid = threadIdx.x;
    int m0 = blockIdx.y * BM;
    int n0 = blockIdx.x * BN;
    int aRow = tid >> 1, aCol = (tid & 1) * 4;
    int tx = tid & 15, ty = tid >> 4;

    ull acc2[8][4];
    #pragma unroll
    for (int i = 0; i < 8; i++)
        #pragma unroll
        for (int j = 0; j < 4; j++) acc2[i][j] = 0ULL;

    for (int kt = 0; kt < K1; kt += BK) {
        int k = kt + aCol;
        {
            float4 v = *reinterpret_cast<const float4*>(A1 + (size_t)(m0 + aRow) * K1 + k);
            As[aCol + 0][aRow] = v.x; As[aCol + 1][aRow] = v.y;
            As[aCol + 2][aRow] = v.z; As[aCol + 3][aRow] = v.w;
        }
        {
            float4 v = *reinterpret_cast<const float4*>(B1 + (size_t)(n0 + aRow) * K1 + k);
            Bs[aCol + 0][aRow] = v.x; Bs[aCol + 1][aRow] = v.y;
            Bs[aCol + 2][aRow] = v.z; Bs[aCol + 3][aRow] = v.w;
        }
        __syncthreads();
        #pragma unroll
        for (int kk = 0; kk < BK; kk++) {
            float a[8];
            *reinterpret_cast<float4*>(&a[0]) = *reinterpret_cast<const float4*>(&As[kk][ty * 8]);
            *reinterpret_cast<float4*>(&a[4]) = *reinterpret_cast<const float4*>(&As[kk][ty * 8 + 4]);
            ull b2r[4];
            const ull* bp = reinterpret_cast<const ull*>(&Bs[kk][tx * 8]);
            b2r[0] = bp[0]; b2r[1] = bp[1]; b2r[2] = bp[2]; b2r[3] = bp[3];
            #pragma unroll
            for (int i = 0; i < 8; i++) {
                ull ad = pack2(a[i], a[i]);
                #pragma unroll
                for (int j = 0; j < 4; j++)
                    acc2[i][j] = ffma2(ad, b2r[j], acc2[i][j]);
            }
        }
        __syncthreads();
    }
    #pragma unroll
    for (int i = 0; i < 8; i++) {
        int m = m0 + ty * 8 + i;
        #pragma unroll
        for (int jj = 0; jj < 4; jj++) {
            float lo, hi;
            unpack2(acc2[i][jj], lo, hi);
            int n = n0 + tx * 8 + jj * 2;
            C[(size_t)m * N + n]     = lo + b1[n] + b2[n];
            C[(size_t)m * N + n + 1] = hi + b1[n + 1] + b2[n + 1];
        }
    }
}

// ---------------- word bi-LSTM recurrence: 2 clusters of 8 CTAs, 512 thr ----------
// R7 proven layout (broadcast hb reads, q = tid>>7, cluster barrier). Two stages
// per step instead of three: matvec -> partial[], ONE __syncthreads, then warp 0
// does the quarter-reduce (16 conflict-free LDS), gate nonlinearities, cell
// update, g_out store, and the 8 DSMEM h broadcasts.
__global__ void __cluster_dims__(8, 1, 1) __launch_bounds__(512, 1)
k_word_lstm(const float* __restrict__ Whh_f, const float* __restrict__ Whh_b) {
    __shared__ __align__(16) float hb[2][HH];
    __shared__ float partial[512];

    unsigned rank;
    asm("mov.u32 %0, %%cluster_ctarank;" : "=r"(rank));
    int dir = blockIdx.x / 8;                   // 0 = fwd, 1 = bwd
    const float* Whh = dir ? Whh_b : Whh_f;
    const float* xg  = dir ? g_xgb : g_xgf;

    int tid = threadIdx.x;
    int p   = tid & 127;       // gate-row within CTA: gate*32 + jj
    int q   = tid >> 7;        // k-quarter (0..3)
    int gte = p >> 5;
    int jj  = p & 31;
    int grow = gte * HH + (int)rank * 32 + jj;  // row in Whh[1024][256]

    ull w2[32];
    const float4* wsrc = reinterpret_cast<const float4*>(Whh + (size_t)grow * HH + q * 64);
    #pragma unroll
    for (int i = 0; i < 16; i++) {
        float4 f = wsrc[i];
        w2[2 * i]     = pack2(f.x, f.y);
        w2[2 * i + 1] = pack2(f.z, f.w);
    }

    int lane = tid & 31;
    // precomputed DSMEM peer addresses (meaningful for lanes of warp 0)
    unsigned raA[8], raB[8];
    {
        unsigned loff0 = (unsigned)__cvta_generic_to_shared(&hb[0][rank * 32 + lane]);
        unsigned loff1 = (unsigned)__cvta_generic_to_shared(&hb[1][rank * 32 + lane]);
        #pragma unroll
        for (int peer = 0; peer < 8; ++peer) {
            asm("mapa.shared::cluster.u32 %0, %1, %2;" : "=r"(raA[peer]) : "r"(loff0), "r"(peer));
            asm("mapa.shared::cluster.u32 %0, %1, %2;" : "=r"(raB[peer]) : "r"(loff1), "r"(peer));
        }
    }

    if (tid < HH) hb[0][tid] = 0.f;
    __syncthreads();
    asm volatile("barrier.cluster.arrive.aligned;" ::: "memory");
    asm volatile("barrier.cluster.wait.aligned;"   ::: "memory");

    float c_reg = 0.f;
    int par = 0;
    const int xbase = (int)rank * 32 + lane;   // x-gate column base (warp-0 lanes)
    float xv0 = 0.f, xv1 = 0.f, xv2 = 0.f, xv3 = 0.f;
    if (tid < 32) {
        size_t r0 = (size_t)(dir ? (S - 1) : 0) * G4HH + xbase;
        xv0 = __ldg(&xg[r0]);       xv1 = __ldg(&xg[r0 + 256]);
        xv2 = __ldg(&xg[r0 + 512]); xv3 = __ldg(&xg[r0 + 768]);
    }

    for (int t = 0; t < S; ++t) {
        int row = dir ? (S - 1 - t) : t;

        const ull* hv = reinterpret_cast<const ull*>(&hb[par][q * 64]);
        ull a0 = 0ULL, a1 = 0ULL, a2 = 0ULL, a3 = 0ULL;
        #pragma unroll
        for (int i = 0; i < 32; i += 4) {
            a0 = ffma2(w2[i + 0], hv[i + 0], a0);
            a1 = ffma2(w2[i + 1], hv[i + 1], a1);
            a2 = ffma2(w2[i + 2], hv[i + 2], a2);
            a3 = ffma2(w2[i + 3], hv[i + 3], a3);
        }
        float l0, h0f, l1, h1f, l2, h2f, l3, h3f;
        unpack2(a0, l0, h0f); unpack2(a1, l1, h1f);
        unpack2(a2, l2, h2f); unpack2(a3, l3, h3f);
        partial[tid] = ((l0 + h0f) + (l1 + h1f)) + ((l2 + h2f) + (l3 + h3f));

        // rolling prefetch of next step's x-gates (warp-0 lanes, 4 coalesced loads)
        float nx0 = 0.f, nx1 = 0.f, nx2 = 0.f, nx3 = 0.f;
        if (tid < 32 && t + 1 < S) {
            int rn = dir ? (S - 2 - t) : (t + 1);
            size_t rb = (size_t)rn * G4HH + xbase;
            nx0 = __ldg(&xg[rb]);       nx1 = __ldg(&xg[rb + 256]);
            nx2 = __ldg(&xg[rb + 512]); nx3 = __ldg(&xg[rb + 768]);
        }
        __syncthreads();
        if (tid < 32) {
            float p0 = (partial[lane]       + partial[lane + 128])
                     + (partial[lane + 256] + partial[lane + 384]);
            float p1 = (partial[32 + lane]       + partial[32 + lane + 128])
                     + (partial[32 + lane + 256] + partial[32 + lane + 384]);
            float p2 = (partial[64 + lane]       + partial[64 + lane + 128])
                     + (partial[64 + lane + 256] + partial[64 + lane + 384]);
            float p3 = (partial[96 + lane]       + partial[96 + lane + 128])
                     + (partial[96 + lane + 256] + partial[96 + lane + 384]);
            float iv = fsig(p0 + xv0);
            float fv = fsig(p1 + xv1);
            float gg = ftanh(p2 + xv2);
            float ov = fsig(p3 + xv3);
            c_reg = fv * c_reg + iv * gg;
            float hnew = ov * ftanh(c_reg);
            g_out[(size_t)row * H + dir * HH + rank * 32 + lane] = hnew;
            if (par == 0) {
                #pragma unroll
                for (int peer = 0; peer < 8; ++peer)
                    asm volatile("st.shared::cluster.f32 [%0], %1;"
                                 :: "r"(raB[peer]), "f"(hnew) : "memory");
            } else {
                #pragma unroll
                for (int peer = 0; peer < 8; ++peer)
                    asm volatile("st.shared::cluster.f32 [%0], %1;"
                                 :: "r"(raA[peer]), "f"(hnew) : "memory");
            }
        }
        asm volatile("barrier.cluster.arrive.aligned;" ::: "memory");
        asm volatile("barrier.cluster.wait.aligned;"   ::: "memory");
        par ^= 1;
        xv0 = nx0; xv1 = nx1; xv2 = nx2; xv3 = nx3;
    }
}

// ---------------- output heads: logits + log_softmax ----------------
__global__ void k_logits(const float* __restrict__ W,   // [C,512]
                         const float* __restrict__ bias,
                         float* __restrict__ dst, int C) {
    __shared__ float row[H];
    __shared__ float red[64];
    int s = blockIdx.x, tid = threadIdx.x;
    for (int k = tid; k < H; k += blockDim.x) row[k] = g_out[(size_t)s * H + k];
    __syncthreads();
    float acc = bias[tid];
    const float4* w4 = reinterpret_cast<const float4*>(W + (size_t)tid * H);
    const float4* r4 = reinterpret_cast<const float4*>(row);
    #pragma unroll 8
    for (int q = 0; q < H / 4; q++) {
        float4 w = w4[q], r = r4[q];
        acc += w.x * r.x + w.y * r.y + w.z * r.z + w.w * r.w;
    }
    red[tid] = acc;
    __syncthreads();
    for (int off = C >> 1; off; off >>= 1) {
        if (tid < off) red[tid] = fmaxf(red[tid], red[tid + off]);
        __syncthreads();
    }
    float mx = red[0];
    __syncthreads();
    red[tid] = expf(acc - mx);
    __syncthreads();
    for (int off = C >> 1; off; off >>= 1) {
        if (tid < off) red[tid] += red[tid + off];
        __syncthreads();
    }
    float lse = mx + logf(red[0]);
    dst[(size_t)s * C + tid] = acc - lse;
}

// ---------------- launch ----------------
extern "C" void kernel_launch(void* const* d_in, const int* in_sizes, int n_in,
                              void* d_out, int out_size) {
    const int*   word_seq   = (const int*)  d_in[0];
    const int*   chars      = (const int*)  d_in[1];
    const int*   char_lens  = (const int*)  d_in[2];
    const int*   feat_seq   = (const int*)  d_in[3];
    const float* char_emb   = (const float*)d_in[4];
    const float* word_emb   = (const float*)d_in[5];
    const float* prefix_emb = (const float*)d_in[6];
    const float* Wih_c = (const float*)d_in[7];
    const float* Whh_c = (const float*)d_in[8];
    const float* bih_c = (const float*)d_in[9];
    const float* bhh_c = (const float*)d_in[10];
    const float* Wih_f = (const float*)d_in[11];
    const float* Whh_f = (const float*)d_in[12];
    const float* bih_f = (const float*)d_in[13];
    const float* bhh_f = (const float*)d_in[14];
    const float* Wih_b = (const float*)d_in[15];
    const float* Whh_b = (const float*)d_in[16];
    const float* bih_b = (const float*)d_in[17];
    const float* bhh_b = (const float*)d_in[18];
    const float* Wpos  = (const float*)d_in[19];
    const float* bpos  = (const float*)d_in[20];
    const float* Wner  = (const float*)d_in[21];
    const float* bner  = (const float*)d_in[22];
    float* out = (float*)d_out;

    float *p_Xc, *p_hA, *p_hB, *p_wc, *p_xgf, *p_xgb;
    cudaGetSymbolAddress((void**)&p_Xc,  g_Xc);
    cudaGetSymbolAddress((void**)&p_hA,  g_hA);
    cudaGetSymbolAddress((void**)&p_hB,  g_hB);
    cudaGetSymbolAddress((void**)&p_wc,  g_wc);
    cudaGetSymbolAddress((void**)&p_xgf, g_xgf);
    cudaGetSymbolAddress((void**)&p_xgb, g_xgb);

    // launches 1-3: sort, fused prep, gather
    k_sort<<<1, 256>>>(char_lens);
    k_prep_all<<<5120 + 8 + 2048, 256>>>(Wih_c, Whh_c, bih_c, bhh_c,
                                         feat_seq, prefix_emb);
    k_gather_xc<<<(L * S * 32) / 256, 256>>>(chars, char_emb);

    // char LSTM: 16 fused steps, h ping-pong, early-exit beyond cnt[t]
    dim3 gridC(G4H / 128, S / 128);
    for (int t = 0; t < L; ++t) {
        float* hcur = (t & 1) ? p_hB : p_hA;
        float* hnxt = (t & 1) ? p_hA : p_hB;
        k_char_step<<<gridC, 256>>>(p_Xc + (size_t)t * S * EC, hcur, hnxt, t);
    }

    // word LSTM input + merged x-gate precompute (fwd+bwd in one launch)
    k_build_wc<<<(S * 256) / 256, 256>>>(word_seq, word_emb);
    dim3 gridX(G4HH / 128, S / 128, 2);
    gemm_xg<<<gridX, 256>>>(p_wc, Wih_f, Wih_b,
                            bih_f, bhh_f, bih_b, bhh_b,
                            p_xgf, p_xgb);

    // sequential bi-LSTM recurrence (2 clusters of 8 CTAs, fwd + bwd concurrent)
    k_word_lstm<<<16, 512>>>(Whh_f, Whh_b);

    // output heads
    k_logits<<<S, NPOS>>>(Wpos, bpos, out, NPOS);
    k_logits<<<S, NNER>>>(Wner, bner, out + (size_t)S * NPOS, NNER);

    (void)in_sizes; (void)n_in; (void)out_size;
}